// round 15
// baseline (speedup 1.0000x reference)
#include <cuda_runtime.h>
#include <cuda_bf16.h>
#include <cstdint>

// Problem constants
#define BATCH 8
#define M_    4096   // H*W
#define C_    256    // feature dim
#define NPOOL 256
#define NTILE 32                      // M_/128
#define NTRI  (NTILE * (NTILE + 1) / 2)   // 528 lower-triangle tiles

// Scratch (device globals: allocation-free rule)
__device__ float    g_corr[(size_t)BATCH * M_ * M_];            // 512 MB
__device__ uint32_t g_h[(size_t)BATCH * M_ * C_ / 2];           // bf16 hi, 16 MB
__device__ uint32_t g_l[(size_t)BATCH * M_ * C_ / 2];           // bf16 lo, 16 MB

// ---------------------------------------------------------------------------
// Kernel 0: fp32 -> (H, L) bf16 split, plain row-major [b][m][c]
// ---------------------------------------------------------------------------
__global__ __launch_bounds__(256) void convert_kernel(const float* __restrict__ x) {
    const int idx = blockIdx.x * 256 + threadIdx.x;
    float2 v = ((const float2*)x)[idx];

    __nv_bfloat16 h0 = __float2bfloat16(v.x);
    __nv_bfloat16 h1 = __float2bfloat16(v.y);
    __nv_bfloat16 l0 = __float2bfloat16(v.x - __bfloat162float(h0));
    __nv_bfloat16 l1 = __float2bfloat16(v.y - __bfloat162float(h1));

    g_h[idx] = (uint32_t)__bfloat16_as_ushort(h0) | ((uint32_t)__bfloat16_as_ushort(h1) << 16);
    g_l[idx] = (uint32_t)__bfloat16_as_ushort(l0) | ((uint32_t)__bfloat16_as_ushort(l1) << 16);
}

// ---------------------------------------------------------------------------
// mma.sync helpers
// ---------------------------------------------------------------------------
__device__ __forceinline__ uint32_t smem_u32(const void* p) {
    uint32_t a;
    asm("{ .reg .u64 t; cvta.to.shared.u64 t, %1; cvt.u32.u64 %0, t; }" : "=r"(a) : "l"(p));
    return a;
}
__device__ __forceinline__ void ldsm_x4(uint32_t& r0, uint32_t& r1, uint32_t& r2, uint32_t& r3,
                                        uint32_t addr) {
    asm volatile("ldmatrix.sync.aligned.m8n8.x4.shared.b16 {%0,%1,%2,%3}, [%4];"
                 : "=r"(r0), "=r"(r1), "=r"(r2), "=r"(r3) : "r"(addr));
}
__device__ __forceinline__ void mma_bf16(float* d, const uint32_t* a, const uint32_t* b) {
    asm volatile("mma.sync.aligned.m16n8k16.row.col.f32.bf16.bf16.f32 "
                 "{%0,%1,%2,%3}, {%4,%5,%6,%7}, {%8,%9}, {%0,%1,%2,%3};"
                 : "+f"(d[0]), "+f"(d[1]), "+f"(d[2]), "+f"(d[3])
                 : "r"(a[0]), "r"(a[1]), "r"(a[2]), "r"(a[3]), "r"(b[0]), "r"(b[1]));
}

// XOR-swizzled smem offset: 64B rows of 4x16B chunks, chunk ^= (row>>1)&3.
__device__ __forceinline__ uint32_t swz(uint32_t row, uint32_t chunk) {
    return row * 64u + ((chunk ^ (row >> 1)) & 3u) * 16u;
}

// ---------------------------------------------------------------------------
// Kernel 1: bf16-split GEMM, lower-triangle tiles (round-10 measured-best).
// ---------------------------------------------------------------------------
#define TILE_SM (128 * 64)        // 8192 B per operand tile
#define STG_P   33                // transpose stage pitch (floats)

union SmemU {
    unsigned char ops[4 * TILE_SM];        // Ah, Al, Bh, Bl (32 KB)
    float stage[128 * STG_P];              // 16.9 KB transpose stage
};

__global__ __launch_bounds__(256) void gemm_mma_kernel() {
    __shared__ __align__(16) SmemU smu;
    unsigned char* sm = smu.ops;

    const int t    = threadIdx.x;
    const int wid  = t >> 5;
    const int lane = t & 31;
    const int b    = blockIdx.z;

    int ti = (int)((sqrtf(8.0f * blockIdx.x + 1.0f) - 1.0f) * 0.5f);
    while ((ti + 1) * (ti + 2) / 2 <= (int)blockIdx.x) ti++;
    while (ti * (ti + 1) / 2 > (int)blockIdx.x) ti--;
    const int tj = blockIdx.x - ti * (ti + 1) / 2;

    const uint32_t sbase = smem_u32(sm);
    const uint32_t OFF_AH = 0, OFF_AL = TILE_SM, OFF_BH = 2 * TILE_SM, OFF_BL = 3 * TILE_SM;

    const unsigned char* gh = (const unsigned char*)g_h;
    const unsigned char* gl = (const unsigned char*)g_l;
    const size_t rowA = (size_t)(b * M_ + ti * 128);
    const size_t rowB = (size_t)(b * M_ + tj * 128);

    const int mw = (wid & 1) * 64;
    const int nw = (wid >> 1) * 32;

    float acc[4][4][4];
#pragma unroll
    for (int i = 0; i < 4; i++)
#pragma unroll
        for (int j = 0; j < 4; j++)
#pragma unroll
            for (int c = 0; c < 4; c++) acc[i][j][c] = 0.0f;

    for (int k0 = 0; k0 < C_; k0 += 32) {
#pragma unroll
        for (int j = 0; j < 2; j++) {
            const int q = j * 256 + t;
            const int r = q >> 2;
            const int c = q & 3;
            const size_t gbyteA = (rowA + r) * (C_ * 2) + (size_t)(k0 + c * 8) * 2;
            const size_t gbyteB = (rowB + r) * (C_ * 2) + (size_t)(k0 + c * 8) * 2;
            const uint32_t so = swz((uint32_t)r, (uint32_t)c);
            *(float4*)(sm + OFF_AH + so) = *(const float4*)(gh + gbyteA);
            *(float4*)(sm + OFF_AL + so) = *(const float4*)(gl + gbyteA);
            *(float4*)(sm + OFF_BH + so) = *(const float4*)(gh + gbyteB);
            *(float4*)(sm + OFF_BL + so) = *(const float4*)(gl + gbyteB);
        }
        __syncthreads();

#pragma unroll
        for (int k16 = 0; k16 < 2; k16++) {
            uint32_t bh[4][2], bl[4][2];
#pragma unroll
            for (int jb = 0; jb < 2; jb++) {
                const uint32_t brow = (uint32_t)(nw + jb * 16 + (lane & 7) +
                                                 ((lane >> 4) & 1) * 8);
                const uint32_t bchk = (uint32_t)(k16 * 2 + ((lane >> 3) & 1));
                uint32_t r0, r1, r2, r3;
                ldsm_x4(r0, r1, r2, r3, sbase + OFF_BH + swz(brow, bchk));
                bh[jb * 2 + 0][0] = r0; bh[jb * 2 + 0][1] = r1;
                bh[jb * 2 + 1][0] = r2; bh[jb * 2 + 1][1] = r3;
                ldsm_x4(r0, r1, r2, r3, sbase + OFF_BL + swz(brow, bchk));
                bl[jb * 2 + 0][0] = r0; bl[jb * 2 + 0][1] = r1;
                bl[jb * 2 + 1][0] = r2; bl[jb * 2 + 1][1] = r3;
            }
            uint32_t a[4][4];
#pragma unroll
            for (int i = 0; i < 4; i++) {
                const uint32_t arow = (uint32_t)(mw + i * 16 + (lane & 15));
                const uint32_t achk = (uint32_t)(k16 * 2 + ((lane >> 4) & 1));
                ldsm_x4(a[i][0], a[i][1], a[i][2], a[i][3], sbase + OFF_AH + swz(arow, achk));
            }
#pragma unroll
            for (int i = 0; i < 4; i++)
#pragma unroll
                for (int j = 0; j < 4; j++) {
                    mma_bf16(acc[i][j], a[i], bh[j]);
                    mma_bf16(acc[i][j], a[i], bl[j]);
                }
#pragma unroll
            for (int i = 0; i < 4; i++) {
                const uint32_t arow = (uint32_t)(mw + i * 16 + (lane & 15));
                const uint32_t achk = (uint32_t)(k16 * 2 + ((lane >> 4) & 1));
                ldsm_x4(a[i][0], a[i][1], a[i][2], a[i][3], sbase + OFF_AL + swz(arow, achk));
            }
#pragma unroll
            for (int i = 0; i < 4; i++)
#pragma unroll
                for (int j = 0; j < 4; j++)
                    mma_bf16(acc[i][j], a[i], bh[j]);
        }
        __syncthreads();
    }

    const float scale = 1.0f / 256.0f;
#pragma unroll
    for (int i = 0; i < 4; i++)
#pragma unroll
        for (int j = 0; j < 4; j++)
#pragma unroll
            for (int c = 0; c < 4; c++) acc[i][j][c] *= scale;

    const int g4 = lane >> 2;
    const int t4 = lane & 3;
    float* Cb = g_corr + (size_t)b * M_ * M_;

    const int colb = tj * 128 + nw + t4 * 2;
#pragma unroll
    for (int i = 0; i < 4; i++) {
        const int row0 = ti * 128 + mw + i * 16 + g4;
#pragma unroll
        for (int j = 0; j < 4; j++) {
            float2 v0 = make_float2(acc[i][j][0], acc[i][j][1]);
            float2 v1 = make_float2(acc[i][j][2], acc[i][j][3]);
            *(float2*)(Cb + (size_t)row0 * M_ + colb + j * 8)       = v0;
            *(float2*)(Cb + (size_t)(row0 + 8) * M_ + colb + j * 8) = v1;
        }
    }

    if (ti != tj) {
        for (int ch = 0; ch < 4; ch++) {
            __syncthreads();
            if ((wid >> 1) == ch) {
#pragma unroll
                for (int i = 0; i < 4; i++) {
                    const int r0 = mw + i * 16 + g4;
#pragma unroll
                    for (int j = 0; j < 4; j++) {
                        const int cl = t4 * 2 + j * 8;
                        smu.stage[r0 * STG_P + cl]           = acc[i][j][0];
                        smu.stage[r0 * STG_P + cl + 1]       = acc[i][j][1];
                        smu.stage[(r0 + 8) * STG_P + cl]     = acc[i][j][2];
                        smu.stage[(r0 + 8) * STG_P + cl + 1] = acc[i][j][3];
                    }
                }
            }
            __syncthreads();
#pragma unroll
            for (int s = 0; s < 4; s++) {
                const int cc = wid + s * 8;
                float* dst = Cb + (size_t)(tj * 128 + ch * 32 + cc) * M_ + ti * 128;
#pragma unroll
                for (int k = 0; k < 4; k++)
                    dst[lane + 32 * k] = smu.stage[(lane + 32 * k) * STG_P + cc];
            }
        }
    }
}

// ---------------------------------------------------------------------------
// Kernel 2: exact percentile selection, v3 (round-10 measured-best).
// ---------------------------------------------------------------------------
#define NBIN 2048
#define PADI(i) ((i) + ((i) >> 5))

__global__ __launch_bounds__(256) void select_kernel(float* __restrict__ out) {
    __shared__ uint32_t keys[M_];              // 16 KB, [j*256 + t]
    __shared__ uint32_t pref[PADI(NBIN) + 1];  // padded counts->prefix->cursors
    __shared__ uint32_t cand[M_];              // 16 KB bucket-grouped keys
    __shared__ uint32_t wsum[8];
    __shared__ float    fred[16];
    __shared__ float    s_vmin, s_vmax;

    const int t = threadIdx.x;
    const int row = blockIdx.x;
    const float* __restrict__ src = g_corr + (size_t)row * M_;

    float v[16];
#pragma unroll
    for (int i = 0; i < 4; i++) {
        float4 w = ((const float4*)src)[i * 256 + t];
        v[i * 4 + 0] = w.x; v[i * 4 + 1] = w.y;
        v[i * 4 + 2] = w.z; v[i * 4 + 3] = w.w;
    }

    for (int i = t; i < PADI(NBIN) + 1; i += 256) pref[i] = 0;

    float lmin = v[0], lmax = v[0];
#pragma unroll
    for (int i = 1; i < 16; i++) { lmin = fminf(lmin, v[i]); lmax = fmaxf(lmax, v[i]); }
#pragma unroll
    for (int o = 16; o > 0; o >>= 1) {
        lmin = fminf(lmin, __shfl_xor_sync(0xFFFFFFFFu, lmin, o));
        lmax = fmaxf(lmax, __shfl_xor_sync(0xFFFFFFFFu, lmax, o));
    }
    if ((t & 31) == 0) { fred[t >> 5] = lmin; fred[8 + (t >> 5)] = lmax; }
    __syncthreads();
    if (t == 0) {
        float a = fred[0], bb = fred[8];
        for (int i = 1; i < 8; i++) { a = fminf(a, fred[i]); bb = fmaxf(bb, fred[8 + i]); }
        s_vmin = a; s_vmax = bb;
    }
    __syncthreads();
    const float vmin = s_vmin, vmax = s_vmax;

    if (!(vmax > vmin)) {                 // degenerate: all equal (uniform branch)
        out[(size_t)row * NPOOL + t] = vmin;
        return;
    }

    const float bscale = (float)NBIN / (vmax - vmin);
#pragma unroll
    for (int i = 0; i < 16; i++) {
        int bb = (int)((v[i] - vmin) * bscale);
        bb = bb > NBIN - 1 ? NBIN - 1 : (bb < 0 ? 0 : bb);
        uint32_t u = __float_as_uint(v[i]);
        keys[i * 256 + t] = u ^ ((u >> 31) ? 0xFFFFFFFFu : 0x80000000u);
        atomicAdd(&pref[PADI(bb)], 1u);
    }
    __syncthreads();

    {
        uint32_t cnt[8], s = 0;
#pragma unroll
        for (int j = 0; j < 8; j++) cnt[j] = pref[PADI(t * 8 + j)];
#pragma unroll
        for (int j = 0; j < 8; j++) { uint32_t x = cnt[j]; cnt[j] = s; s += x; }
        uint32_t tot = s;
#pragma unroll
        for (int o = 1; o < 32; o <<= 1) {
            uint32_t x = __shfl_up_sync(0xFFFFFFFFu, s, o);
            if ((t & 31) >= o) s += x;
        }
        uint32_t wex = s - tot;
        if ((t & 31) == 31) wsum[t >> 5] = s;
        __syncthreads();
        uint32_t base = 0;
        for (int w = 0; w < (t >> 5); w++) base += wsum[w];
#pragma unroll
        for (int j = 0; j < 8; j++) pref[PADI(t * 8 + j)] = base + wex + cnt[j];
        if (t == 0) pref[PADI(NBIN)] = M_;
    }
    __syncthreads();

    const float step = 4094.0f / 255.0f;
    int q = (int)rintf(fmaf((float)t, step, 1.0f));
    if (q < 1) q = 1; if (q > M_ - 1) q = M_ - 1;
    const uint32_t a = (uint32_t)(M_ - 1 - q);
    int lo = 0, hi = NBIN - 1;
    while (lo < hi) {
        int mid = (lo + hi + 1) >> 1;
        if (pref[PADI(mid)] <= a) lo = mid; else hi = mid - 1;
    }
    const uint32_t mybase = pref[PADI(lo)];
    const uint32_t n  = pref[PADI(lo + 1)] - mybase;
    const uint32_t la = a - mybase;
    __syncthreads();

#pragma unroll
    for (int i = 0; i < 16; i++) {
        const uint32_t k = keys[i * 256 + t];
        const uint32_t u = (k & 0x80000000u) ? (k ^ 0x80000000u) : ~k;
        const float val = __uint_as_float(u);
        int bb = (int)((val - vmin) * bscale);
        bb = bb > NBIN - 1 ? NBIN - 1 : (bb < 0 ? 0 : bb);
        uint32_t pos = atomicAdd(&pref[PADI(bb)], 1u);
        cand[pos] = k;
    }
    __syncthreads();

    uint32_t myval = cand[mybase];
    for (uint32_t i = 0; i < n; i++) {
        uint32_t ki = cand[mybase + i];
        uint32_t r = 0;
        for (uint32_t j = 0; j < n; j++) {
            uint32_t kj = cand[mybase + j];
            r += (kj < ki) || (kj == ki && j < i);
        }
        if (r == la) { myval = ki; break; }
    }
    uint32_t ub = (myval & 0x80000000u) ? (myval ^ 0x80000000u) : ~myval;
    out[(size_t)row * NPOOL + t] = __uint_as_float(ub);
}

// ---------------------------------------------------------------------------
// Launch — MEASUREMENT ROUND: select_kernel launched twice (idempotent).
// T_total = T_base(1367-equiv) + S_select; pins the GEMM/select cost split
// that five rounds of blind select redesigns failed to identify.
// ---------------------------------------------------------------------------
extern "C" void kernel_launch(void* const* d_in, const int* in_sizes, int n_in,
                              void* d_out, int out_size) {
    (void)in_sizes; (void)n_in; (void)out_size;
    const float* x = (const float*)d_in[0];
    float* out = (float*)d_out;

    convert_kernel<<<(BATCH * M_ * C_ / 2) / 256, 256>>>(x);

    dim3 ggrid(NTRI, 1, BATCH);
    gemm_mma_kernel<<<ggrid, 256>>>();

    select_kernel<<<BATCH * M_, 256>>>(out);
    select_kernel<<<BATCH * M_, 256>>>(out);   // idempotent re-run: Δt == S_select
}

// round 16
// speedup vs baseline: 1.7522x; 1.7522x over previous
#include <cuda_runtime.h>
#include <cuda_bf16.h>
#include <cstdint>

// Problem constants
#define BATCH 8
#define M_    4096   // H*W
#define C_    256    // feature dim
#define NPOOL 256
#define NTILE 32                      // M_/128
#define NTRI  (NTILE * (NTILE + 1) / 2)   // 528 lower-triangle tiles

// Scratch (device globals: allocation-free rule)
__device__ float    g_corr[(size_t)BATCH * M_ * M_];            // 512 MB
__device__ uint32_t g_h[(size_t)BATCH * M_ * C_ / 2];           // bf16 hi, 16 MB
__device__ uint32_t g_l[(size_t)BATCH * M_ * C_ / 2];           // bf16 lo, 16 MB

// ---------------------------------------------------------------------------
// Kernel 0: fp32 -> (H, L) bf16 split, plain row-major [b][m][c]
// ---------------------------------------------------------------------------
__global__ __launch_bounds__(256) void convert_kernel(const float* __restrict__ x) {
    const int idx = blockIdx.x * 256 + threadIdx.x;
    float2 v = ((const float2*)x)[idx];

    __nv_bfloat16 h0 = __float2bfloat16(v.x);
    __nv_bfloat16 h1 = __float2bfloat16(v.y);
    __nv_bfloat16 l0 = __float2bfloat16(v.x - __bfloat162float(h0));
    __nv_bfloat16 l1 = __float2bfloat16(v.y - __bfloat162float(h1));

    g_h[idx] = (uint32_t)__bfloat16_as_ushort(h0) | ((uint32_t)__bfloat16_as_ushort(h1) << 16);
    g_l[idx] = (uint32_t)__bfloat16_as_ushort(l0) | ((uint32_t)__bfloat16_as_ushort(l1) << 16);
}

// ---------------------------------------------------------------------------
// mma.sync helpers
// ---------------------------------------------------------------------------
__device__ __forceinline__ uint32_t smem_u32(const void* p) {
    uint32_t a;
    asm("{ .reg .u64 t; cvta.to.shared.u64 t, %1; cvt.u32.u64 %0, t; }" : "=r"(a) : "l"(p));
    return a;
}
__device__ __forceinline__ void ldsm_x4(uint32_t& r0, uint32_t& r1, uint32_t& r2, uint32_t& r3,
                                        uint32_t addr) {
    asm volatile("ldmatrix.sync.aligned.m8n8.x4.shared.b16 {%0,%1,%2,%3}, [%4];"
                 : "=r"(r0), "=r"(r1), "=r"(r2), "=r"(r3) : "r"(addr));
}
__device__ __forceinline__ void mma_bf16(float* d, const uint32_t* a, const uint32_t* b) {
    asm volatile("mma.sync.aligned.m16n8k16.row.col.f32.bf16.bf16.f32 "
                 "{%0,%1,%2,%3}, {%4,%5,%6,%7}, {%8,%9}, {%0,%1,%2,%3};"
                 : "+f"(d[0]), "+f"(d[1]), "+f"(d[2]), "+f"(d[3])
                 : "r"(a[0]), "r"(a[1]), "r"(a[2]), "r"(a[3]), "r"(b[0]), "r"(b[1]));
}

// XOR-swizzled smem offset: 64B rows of 4x16B chunks, chunk ^= (row>>1)&3.
__device__ __forceinline__ uint32_t swz(uint32_t row, uint32_t chunk) {
    return row * 64u + ((chunk ^ (row >> 1)) & 3u) * 16u;
}

// ---------------------------------------------------------------------------
// Kernel 1: bf16-split GEMM, lower-triangle tiles (round-10 measured-best).
// ---------------------------------------------------------------------------
#define TILE_SM (128 * 64)        // 8192 B per operand tile
#define STG_P   33                // transpose stage pitch (floats)

union SmemU {
    unsigned char ops[4 * TILE_SM];        // Ah, Al, Bh, Bl (32 KB)
    float stage[128 * STG_P];              // 16.9 KB transpose stage
};

__global__ __launch_bounds__(256) void gemm_mma_kernel() {
    __shared__ __align__(16) SmemU smu;
    unsigned char* sm = smu.ops;

    const int t    = threadIdx.x;
    const int wid  = t >> 5;
    const int lane = t & 31;
    const int b    = blockIdx.z;

    int ti = (int)((sqrtf(8.0f * blockIdx.x + 1.0f) - 1.0f) * 0.5f);
    while ((ti + 1) * (ti + 2) / 2 <= (int)blockIdx.x) ti++;
    while (ti * (ti + 1) / 2 > (int)blockIdx.x) ti--;
    const int tj = blockIdx.x - ti * (ti + 1) / 2;

    const uint32_t sbase = smem_u32(sm);
    const uint32_t OFF_AH = 0, OFF_AL = TILE_SM, OFF_BH = 2 * TILE_SM, OFF_BL = 3 * TILE_SM;

    const unsigned char* gh = (const unsigned char*)g_h;
    const unsigned char* gl = (const unsigned char*)g_l;
    const size_t rowA = (size_t)(b * M_ + ti * 128);
    const size_t rowB = (size_t)(b * M_ + tj * 128);

    const int mw = (wid & 1) * 64;
    const int nw = (wid >> 1) * 32;

    float acc[4][4][4];
#pragma unroll
    for (int i = 0; i < 4; i++)
#pragma unroll
        for (int j = 0; j < 4; j++)
#pragma unroll
            for (int c = 0; c < 4; c++) acc[i][j][c] = 0.0f;

    for (int k0 = 0; k0 < C_; k0 += 32) {
#pragma unroll
        for (int j = 0; j < 2; j++) {
            const int q = j * 256 + t;
            const int r = q >> 2;
            const int c = q & 3;
            const size_t gbyteA = (rowA + r) * (C_ * 2) + (size_t)(k0 + c * 8) * 2;
            const size_t gbyteB = (rowB + r) * (C_ * 2) + (size_t)(k0 + c * 8) * 2;
            const uint32_t so = swz((uint32_t)r, (uint32_t)c);
            *(float4*)(sm + OFF_AH + so) = *(const float4*)(gh + gbyteA);
            *(float4*)(sm + OFF_AL + so) = *(const float4*)(gl + gbyteA);
            *(float4*)(sm + OFF_BH + so) = *(const float4*)(gh + gbyteB);
            *(float4*)(sm + OFF_BL + so) = *(const float4*)(gl + gbyteB);
        }
        __syncthreads();

#pragma unroll
        for (int k16 = 0; k16 < 2; k16++) {
            uint32_t bh[4][2], bl[4][2];
#pragma unroll
            for (int jb = 0; jb < 2; jb++) {
                const uint32_t brow = (uint32_t)(nw + jb * 16 + (lane & 7) +
                                                 ((lane >> 4) & 1) * 8);
                const uint32_t bchk = (uint32_t)(k16 * 2 + ((lane >> 3) & 1));
                uint32_t r0, r1, r2, r3;
                ldsm_x4(r0, r1, r2, r3, sbase + OFF_BH + swz(brow, bchk));
                bh[jb * 2 + 0][0] = r0; bh[jb * 2 + 0][1] = r1;
                bh[jb * 2 + 1][0] = r2; bh[jb * 2 + 1][1] = r3;
                ldsm_x4(r0, r1, r2, r3, sbase + OFF_BL + swz(brow, bchk));
                bl[jb * 2 + 0][0] = r0; bl[jb * 2 + 0][1] = r1;
                bl[jb * 2 + 1][0] = r2; bl[jb * 2 + 1][1] = r3;
            }
            uint32_t a[4][4];
#pragma unroll
            for (int i = 0; i < 4; i++) {
                const uint32_t arow = (uint32_t)(mw + i * 16 + (lane & 15));
                const uint32_t achk = (uint32_t)(k16 * 2 + ((lane >> 4) & 1));
                ldsm_x4(a[i][0], a[i][1], a[i][2], a[i][3], sbase + OFF_AH + swz(arow, achk));
            }
#pragma unroll
            for (int i = 0; i < 4; i++)
#pragma unroll
                for (int j = 0; j < 4; j++) {
                    mma_bf16(acc[i][j], a[i], bh[j]);
                    mma_bf16(acc[i][j], a[i], bl[j]);
                }
#pragma unroll
            for (int i = 0; i < 4; i++) {
                const uint32_t arow = (uint32_t)(mw + i * 16 + (lane & 15));
                const uint32_t achk = (uint32_t)(k16 * 2 + ((lane >> 4) & 1));
                ldsm_x4(a[i][0], a[i][1], a[i][2], a[i][3], sbase + OFF_AL + swz(arow, achk));
            }
#pragma unroll
            for (int i = 0; i < 4; i++)
#pragma unroll
                for (int j = 0; j < 4; j++)
                    mma_bf16(acc[i][j], a[i], bh[j]);
        }
        __syncthreads();
    }

    const float scale = 1.0f / 256.0f;
#pragma unroll
    for (int i = 0; i < 4; i++)
#pragma unroll
        for (int j = 0; j < 4; j++)
#pragma unroll
            for (int c = 0; c < 4; c++) acc[i][j][c] *= scale;

    const int g4 = lane >> 2;
    const int t4 = lane & 3;
    float* Cb = g_corr + (size_t)b * M_ * M_;

    const int colb = tj * 128 + nw + t4 * 2;
#pragma unroll
    for (int i = 0; i < 4; i++) {
        const int row0 = ti * 128 + mw + i * 16 + g4;
#pragma unroll
        for (int j = 0; j < 4; j++) {
            float2 v0 = make_float2(acc[i][j][0], acc[i][j][1]);
            float2 v1 = make_float2(acc[i][j][2], acc[i][j][3]);
            *(float2*)(Cb + (size_t)row0 * M_ + colb + j * 8)       = v0;
            *(float2*)(Cb + (size_t)(row0 + 8) * M_ + colb + j * 8) = v1;
        }
    }

    if (ti != tj) {
        for (int ch = 0; ch < 4; ch++) {
            __syncthreads();
            if ((wid >> 1) == ch) {
#pragma unroll
                for (int i = 0; i < 4; i++) {
                    const int r0 = mw + i * 16 + g4;
#pragma unroll
                    for (int j = 0; j < 4; j++) {
                        const int cl = t4 * 2 + j * 8;
                        smu.stage[r0 * STG_P + cl]           = acc[i][j][0];
                        smu.stage[r0 * STG_P + cl + 1]       = acc[i][j][1];
                        smu.stage[(r0 + 8) * STG_P + cl]     = acc[i][j][2];
                        smu.stage[(r0 + 8) * STG_P + cl + 1] = acc[i][j][3];
                    }
                }
            }
            __syncthreads();
#pragma unroll
            for (int s = 0; s < 4; s++) {
                const int cc = wid + s * 8;
                float* dst = Cb + (size_t)(tj * 128 + ch * 32 + cc) * M_ + ti * 128;
#pragma unroll
                for (int k = 0; k < 4; k++)
                    dst[lane + 32 * k] = smu.stage[(lane + 32 * k) * STG_P + cc];
            }
        }
    }
}

// ---------------------------------------------------------------------------
// Kernel 2: exact percentile selection, v7 — instruction-diet of v3.
//   ncu (R15): issue 85.4%, alu 65.9% -> ISSUE-BOUND. Cuts vs v3:
//   no key encoding (compare raw floats; equal values interchangeable),
//   no 16KB key staging (phase 2 recomputes bin from register values),
//   histogram iter = 5 ops, scatter iter = 6 ops. smem 41->25 KB.
// ---------------------------------------------------------------------------
#define NBIN 2048
#define PADI(i) ((i) + ((i) >> 5))

__global__ __launch_bounds__(256) void select_kernel(float* __restrict__ out) {
    __shared__ float    cand[M_];              // 16 KB bucket-grouped values
    __shared__ uint32_t pref[PADI(NBIN) + 1];  // padded counts->prefix->cursors
    __shared__ uint32_t wsum[8];
    __shared__ float    fred[16];
    __shared__ float    s_vmin, s_vmax;

    const int t = threadIdx.x;
    const int row = blockIdx.x;
    const float* __restrict__ src = g_corr + (size_t)row * M_;

    float v[16];
#pragma unroll
    for (int i = 0; i < 4; i++) {
        float4 w = ((const float4*)src)[i * 256 + t];
        v[i * 4 + 0] = w.x; v[i * 4 + 1] = w.y;
        v[i * 4 + 2] = w.z; v[i * 4 + 3] = w.w;
    }

    // zero padded counts
    for (int i = t; i < PADI(NBIN) + 1; i += 256) pref[i] = 0;

    // block min/max (shuffle)
    float lmin = v[0], lmax = v[0];
#pragma unroll
    for (int i = 1; i < 16; i++) { lmin = fminf(lmin, v[i]); lmax = fmaxf(lmax, v[i]); }
#pragma unroll
    for (int o = 16; o > 0; o >>= 1) {
        lmin = fminf(lmin, __shfl_xor_sync(0xFFFFFFFFu, lmin, o));
        lmax = fmaxf(lmax, __shfl_xor_sync(0xFFFFFFFFu, lmax, o));
    }
    if ((t & 31) == 0) { fred[t >> 5] = lmin; fred[8 + (t >> 5)] = lmax; }
    __syncthreads();
    if (t == 0) {
        float a = fred[0], bb = fred[8];
        for (int i = 1; i < 8; i++) { a = fminf(a, fred[i]); bb = fmaxf(bb, fred[8 + i]); }
        s_vmin = a; s_vmax = bb;
    }
    __syncthreads();
    const float vmin = s_vmin, vmax = s_vmax;

    if (!(vmax > vmin)) {                 // degenerate: all equal (uniform branch)
        out[(size_t)row * NPOOL + t] = vmin;
        return;
    }

    // phase 1: histogram only — 5 ops per element
    const float bscale = (float)NBIN / (vmax - vmin);
#pragma unroll
    for (int i = 0; i < 16; i++) {
        int bb = (int)((v[i] - vmin) * bscale);
        bb = bb > NBIN - 1 ? NBIN - 1 : (bb < 0 ? 0 : bb);
        atomicAdd(&pref[PADI(bb)], 1u);
    }
    __syncthreads();

    // exclusive prefix: 8 bins/thread (padded, conflict-free) + shuffle scan
    {
        uint32_t cnt[8], s = 0;
#pragma unroll
        for (int j = 0; j < 8; j++) cnt[j] = pref[PADI(t * 8 + j)];
#pragma unroll
        for (int j = 0; j < 8; j++) { uint32_t x = cnt[j]; cnt[j] = s; s += x; }
        uint32_t tot = s;
#pragma unroll
        for (int o = 1; o < 32; o <<= 1) {
            uint32_t x = __shfl_up_sync(0xFFFFFFFFu, s, o);
            if ((t & 31) >= o) s += x;
        }
        uint32_t wex = s - tot;
        if ((t & 31) == 31) wsum[t >> 5] = s;
        __syncthreads();
        uint32_t base = 0;
        for (int w = 0; w < (t >> 5); w++) base += wsum[w];
#pragma unroll
        for (int j = 0; j < 8; j++) pref[PADI(t * 8 + j)] = base + wex + cnt[j];
        if (t == 0) pref[PADI(NBIN)] = M_;
    }
    __syncthreads();

    // rank -> bucket; capture base/n/la BEFORE scatter mutates pref
    const float step = 4094.0f / 255.0f;
    int q = (int)rintf(fmaf((float)t, step, 1.0f));
    if (q < 1) q = 1; if (q > M_ - 1) q = M_ - 1;
    const uint32_t a = (uint32_t)(M_ - 1 - q);
    int lo = 0, hi = NBIN - 1;
    while (lo < hi) {
        int mid = (lo + hi + 1) >> 1;
        if (pref[PADI(mid)] <= a) lo = mid; else hi = mid - 1;
    }
    const uint32_t mybase = pref[PADI(lo)];
    const uint32_t n  = pref[PADI(lo + 1)] - mybase;
    const uint32_t la = a - mybase;
    __syncthreads();                                     // searches done before scatter

    // phase 2: scatter raw values — 6 ops per element (bin recomputed,
    // bit-identical formula; no keys, no staging)
#pragma unroll
    for (int i = 0; i < 16; i++) {
        int bb = (int)((v[i] - vmin) * bscale);
        bb = bb > NBIN - 1 ? NBIN - 1 : (bb < 0 ? 0 : bb);
        uint32_t pos = atomicAdd(&pref[PADI(bb)], 1u);
        cand[pos] = v[i];
    }
    __syncthreads();

    // exact la-th smallest among cand[mybase .. mybase+n) — floats, ties by
    // slot (tied values are bit-identical, so output is exact either way)
    float myval = cand[mybase];
    for (uint32_t i = 0; i < n; i++) {
        float ki = cand[mybase + i];
        uint32_t r = 0;
        for (uint32_t j = 0; j < n; j++) {
            float kj = cand[mybase + j];
            r += (kj < ki) || (kj == ki && j < i);
        }
        if (r == la) { myval = ki; break; }
    }
    out[(size_t)row * NPOOL + t] = myval;
}

// ---------------------------------------------------------------------------
// Launch
// ---------------------------------------------------------------------------
extern "C" void kernel_launch(void* const* d_in, const int* in_sizes, int n_in,
                              void* d_out, int out_size) {
    (void)in_sizes; (void)n_in; (void)out_size;
    const float* x = (const float*)d_in[0];
    float* out = (float*)d_out;

    convert_kernel<<<(BATCH * M_ * C_ / 2) / 256, 256>>>(x);

    dim3 ggrid(NTRI, 1, BATCH);
    gemm_mma_kernel<<<ggrid, 256>>>();

    select_kernel<<<BATCH * M_, 256>>>(out);
}

// round 17
// speedup vs baseline: 2.8135x; 1.6057x over previous
#include <cuda_runtime.h>
#include <cuda_bf16.h>
#include <cstdint>

// Problem constants
#define BATCH 8
#define M_    4096   // H*W
#define C_    256    // feature dim
#define NPOOL 256
#define NTILE 32                      // M_/128
#define NTRI  (NTILE * (NTILE + 1) / 2)   // 528 lower-triangle tiles

// Scratch (device globals: allocation-free rule)
__device__ float    g_corr[(size_t)BATCH * M_ * M_];            // 512 MB
__device__ uint32_t g_h[(size_t)BATCH * M_ * C_ / 2];           // bf16 hi, 16 MB
__device__ uint32_t g_l[(size_t)BATCH * M_ * C_ / 2];           // bf16 lo, 16 MB

// ---------------------------------------------------------------------------
// Kernel 0: fp32 -> (H, L) bf16 split, plain row-major [b][m][c]
// ---------------------------------------------------------------------------
__global__ __launch_bounds__(256) void convert_kernel(const float* __restrict__ x) {
    const int idx = blockIdx.x * 256 + threadIdx.x;
    float2 v = ((const float2*)x)[idx];

    __nv_bfloat16 h0 = __float2bfloat16(v.x);
    __nv_bfloat16 h1 = __float2bfloat16(v.y);
    __nv_bfloat16 l0 = __float2bfloat16(v.x - __bfloat162float(h0));
    __nv_bfloat16 l1 = __float2bfloat16(v.y - __bfloat162float(h1));

    g_h[idx] = (uint32_t)__bfloat16_as_ushort(h0) | ((uint32_t)__bfloat16_as_ushort(h1) << 16);
    g_l[idx] = (uint32_t)__bfloat16_as_ushort(l0) | ((uint32_t)__bfloat16_as_ushort(l1) << 16);
}

// ---------------------------------------------------------------------------
// mma.sync helpers
// ---------------------------------------------------------------------------
__device__ __forceinline__ uint32_t smem_u32(const void* p) {
    uint32_t a;
    asm("{ .reg .u64 t; cvta.to.shared.u64 t, %1; cvt.u32.u64 %0, t; }" : "=r"(a) : "l"(p));
    return a;
}
__device__ __forceinline__ void ldsm_x4(uint32_t& r0, uint32_t& r1, uint32_t& r2, uint32_t& r3,
                                        uint32_t addr) {
    asm volatile("ldmatrix.sync.aligned.m8n8.x4.shared.b16 {%0,%1,%2,%3}, [%4];"
                 : "=r"(r0), "=r"(r1), "=r"(r2), "=r"(r3) : "r"(addr));
}
__device__ __forceinline__ void mma_bf16(float* d, const uint32_t* a, const uint32_t* b) {
    asm volatile("mma.sync.aligned.m16n8k16.row.col.f32.bf16.bf16.f32 "
                 "{%0,%1,%2,%3}, {%4,%5,%6,%7}, {%8,%9}, {%0,%1,%2,%3};"
                 : "+f"(d[0]), "+f"(d[1]), "+f"(d[2]), "+f"(d[3])
                 : "r"(a[0]), "r"(a[1]), "r"(a[2]), "r"(a[3]), "r"(b[0]), "r"(b[1]));
}

// XOR-swizzled smem offset: 64B rows of 4x16B chunks, chunk ^= (row>>1)&3.
__device__ __forceinline__ uint32_t swz(uint32_t row, uint32_t chunk) {
    return row * 64u + ((chunk ^ (row >> 1)) & 3u) * 16u;
}

// ---------------------------------------------------------------------------
// Kernel 1: bf16-split GEMM, lower-triangle tiles (round-10 measured-best).
// ---------------------------------------------------------------------------
#define TILE_SM (128 * 64)        // 8192 B per operand tile
#define STG_P   33                // transpose stage pitch (floats)

union SmemU {
    unsigned char ops[4 * TILE_SM];        // Ah, Al, Bh, Bl (32 KB)
    float stage[128 * STG_P];              // 16.9 KB transpose stage
};

__global__ __launch_bounds__(256) void gemm_mma_kernel() {
    __shared__ __align__(16) SmemU smu;
    unsigned char* sm = smu.ops;

    const int t    = threadIdx.x;
    const int wid  = t >> 5;
    const int lane = t & 31;
    const int b    = blockIdx.z;

    int ti = (int)((sqrtf(8.0f * blockIdx.x + 1.0f) - 1.0f) * 0.5f);
    while ((ti + 1) * (ti + 2) / 2 <= (int)blockIdx.x) ti++;
    while (ti * (ti + 1) / 2 > (int)blockIdx.x) ti--;
    const int tj = blockIdx.x - ti * (ti + 1) / 2;

    const uint32_t sbase = smem_u32(sm);
    const uint32_t OFF_AH = 0, OFF_AL = TILE_SM, OFF_BH = 2 * TILE_SM, OFF_BL = 3 * TILE_SM;

    const unsigned char* gh = (const unsigned char*)g_h;
    const unsigned char* gl = (const unsigned char*)g_l;
    const size_t rowA = (size_t)(b * M_ + ti * 128);
    const size_t rowB = (size_t)(b * M_ + tj * 128);

    const int mw = (wid & 1) * 64;
    const int nw = (wid >> 1) * 32;

    float acc[4][4][4];
#pragma unroll
    for (int i = 0; i < 4; i++)
#pragma unroll
        for (int j = 0; j < 4; j++)
#pragma unroll
            for (int c = 0; c < 4; c++) acc[i][j][c] = 0.0f;

    for (int k0 = 0; k0 < C_; k0 += 32) {
#pragma unroll
        for (int j = 0; j < 2; j++) {
            const int q = j * 256 + t;
            const int r = q >> 2;
            const int c = q & 3;
            const size_t gbyteA = (rowA + r) * (C_ * 2) + (size_t)(k0 + c * 8) * 2;
            const size_t gbyteB = (rowB + r) * (C_ * 2) + (size_t)(k0 + c * 8) * 2;
            const uint32_t so = swz((uint32_t)r, (uint32_t)c);
            *(float4*)(sm + OFF_AH + so) = *(const float4*)(gh + gbyteA);
            *(float4*)(sm + OFF_AL + so) = *(const float4*)(gl + gbyteA);
            *(float4*)(sm + OFF_BH + so) = *(const float4*)(gh + gbyteB);
            *(float4*)(sm + OFF_BL + so) = *(const float4*)(gl + gbyteB);
        }
        __syncthreads();

#pragma unroll
        for (int k16 = 0; k16 < 2; k16++) {
            uint32_t bh[4][2], bl[4][2];
#pragma unroll
            for (int jb = 0; jb < 2; jb++) {
                const uint32_t brow = (uint32_t)(nw + jb * 16 + (lane & 7) +
                                                 ((lane >> 4) & 1) * 8);
                const uint32_t bchk = (uint32_t)(k16 * 2 + ((lane >> 3) & 1));
                uint32_t r0, r1, r2, r3;
                ldsm_x4(r0, r1, r2, r3, sbase + OFF_BH + swz(brow, bchk));
                bh[jb * 2 + 0][0] = r0; bh[jb * 2 + 0][1] = r1;
                bh[jb * 2 + 1][0] = r2; bh[jb * 2 + 1][1] = r3;
                ldsm_x4(r0, r1, r2, r3, sbase + OFF_BL + swz(brow, bchk));
                bl[jb * 2 + 0][0] = r0; bl[jb * 2 + 0][1] = r1;
                bl[jb * 2 + 1][0] = r2; bl[jb * 2 + 1][1] = r3;
            }
            uint32_t a[4][4];
#pragma unroll
            for (int i = 0; i < 4; i++) {
                const uint32_t arow = (uint32_t)(mw + i * 16 + (lane & 15));
                const uint32_t achk = (uint32_t)(k16 * 2 + ((lane >> 4) & 1));
                ldsm_x4(a[i][0], a[i][1], a[i][2], a[i][3], sbase + OFF_AH + swz(arow, achk));
            }
#pragma unroll
            for (int i = 0; i < 4; i++)
#pragma unroll
                for (int j = 0; j < 4; j++) {
                    mma_bf16(acc[i][j], a[i], bh[j]);
                    mma_bf16(acc[i][j], a[i], bl[j]);
                }
#pragma unroll
            for (int i = 0; i < 4; i++) {
                const uint32_t arow = (uint32_t)(mw + i * 16 + (lane & 15));
                const uint32_t achk = (uint32_t)(k16 * 2 + ((lane >> 4) & 1));
                ldsm_x4(a[i][0], a[i][1], a[i][2], a[i][3], sbase + OFF_AL + swz(arow, achk));
            }
#pragma unroll
            for (int i = 0; i < 4; i++)
#pragma unroll
                for (int j = 0; j < 4; j++)
                    mma_bf16(acc[i][j], a[i], bh[j]);
        }
        __syncthreads();
    }

    const float scale = 1.0f / 256.0f;
#pragma unroll
    for (int i = 0; i < 4; i++)
#pragma unroll
        for (int j = 0; j < 4; j++)
#pragma unroll
            for (int c = 0; c < 4; c++) acc[i][j][c] *= scale;

    const int g4 = lane >> 2;
    const int t4 = lane & 3;
    float* Cb = g_corr + (size_t)b * M_ * M_;

    const int colb = tj * 128 + nw + t4 * 2;
#pragma unroll
    for (int i = 0; i < 4; i++) {
        const int row0 = ti * 128 + mw + i * 16 + g4;
#pragma unroll
        for (int j = 0; j < 4; j++) {
            float2 v0 = make_float2(acc[i][j][0], acc[i][j][1]);
            float2 v1 = make_float2(acc[i][j][2], acc[i][j][3]);
            *(float2*)(Cb + (size_t)row0 * M_ + colb + j * 8)       = v0;
            *(float2*)(Cb + (size_t)(row0 + 8) * M_ + colb + j * 8) = v1;
        }
    }

    if (ti != tj) {
        for (int ch = 0; ch < 4; ch++) {
            __syncthreads();
            if ((wid >> 1) == ch) {
#pragma unroll
                for (int i = 0; i < 4; i++) {
                    const int r0 = mw + i * 16 + g4;
#pragma unroll
                    for (int j = 0; j < 4; j++) {
                        const int cl = t4 * 2 + j * 8;
                        smu.stage[r0 * STG_P + cl]           = acc[i][j][0];
                        smu.stage[r0 * STG_P + cl + 1]       = acc[i][j][1];
                        smu.stage[(r0 + 8) * STG_P + cl]     = acc[i][j][2];
                        smu.stage[(r0 + 8) * STG_P + cl + 1] = acc[i][j][3];
                    }
                }
            }
            __syncthreads();
#pragma unroll
            for (int s = 0; s < 4; s++) {
                const int cc = wid + s * 8;
                float* dst = Cb + (size_t)(tj * 128 + ch * 32 + cc) * M_ + ti * 128;
#pragma unroll
                for (int k = 0; k < 4; k++)
                    dst[lane + 32 * k] = smu.stage[(lane + 32 * k) * STG_P + cc];
            }
        }
    }
}

// ---------------------------------------------------------------------------
// Kernel 2: exact percentile selection, v8.
//   R16 falsified the instruction-diet theory: v3==v7 because both share the
//   O(n^2) refinement, which dominates (center linear-bins hold n~16 with
//   2048 bins since vmax~1.0 (self-corr) but sigma~1/16). Fix the lever:
//   NBIN=8192 -> center n~4, warp-max ~8-10 -> refinement ~6x cheaper.
//   Scan = 32 bins/thread, two-pass reload (no reg-array), padded stride.
//   smem ~50 KB dynamic (cand 16 KB + pref 33.8 KB) -> 4 CTAs/SM (~50% occ,
//   which sustained 85% issue in v3).
// ---------------------------------------------------------------------------
#define NBIN 8192
#define PADI(i) ((i) + ((i) >> 5))
#define SEL_SMEM ((16384) + (PADI(NBIN) + 2) * 4)   // cand + pref, bytes

__global__ __launch_bounds__(256) void select_kernel(float* __restrict__ out) {
    extern __shared__ unsigned char dynsm[];
    float*    cand = (float*)dynsm;                    // 16 KB
    uint32_t* pref = (uint32_t*)(dynsm + 16384);       // PADI(NBIN)+1 words

    __shared__ uint32_t wsum[8];
    __shared__ float    fred[16];
    __shared__ float    s_vmin, s_vmax;

    const int t = threadIdx.x;
    const int row = blockIdx.x;
    const float* __restrict__ src = g_corr + (size_t)row * M_;

    float v[16];
#pragma unroll
    for (int i = 0; i < 4; i++) {
        float4 w = ((const float4*)src)[i * 256 + t];
        v[i * 4 + 0] = w.x; v[i * 4 + 1] = w.y;
        v[i * 4 + 2] = w.z; v[i * 4 + 3] = w.w;
    }

    // zero padded counts
    for (int i = t; i < PADI(NBIN) + 1; i += 256) pref[i] = 0;

    // block min/max (shuffle)
    float lmin = v[0], lmax = v[0];
#pragma unroll
    for (int i = 1; i < 16; i++) { lmin = fminf(lmin, v[i]); lmax = fmaxf(lmax, v[i]); }
#pragma unroll
    for (int o = 16; o > 0; o >>= 1) {
        lmin = fminf(lmin, __shfl_xor_sync(0xFFFFFFFFu, lmin, o));
        lmax = fmaxf(lmax, __shfl_xor_sync(0xFFFFFFFFu, lmax, o));
    }
    if ((t & 31) == 0) { fred[t >> 5] = lmin; fred[8 + (t >> 5)] = lmax; }
    __syncthreads();
    if (t == 0) {
        float a = fred[0], bb = fred[8];
        for (int i = 1; i < 8; i++) { a = fminf(a, fred[i]); bb = fmaxf(bb, fred[8 + i]); }
        s_vmin = a; s_vmax = bb;
    }
    __syncthreads();
    const float vmin = s_vmin, vmax = s_vmax;

    if (!(vmax > vmin)) {                 // degenerate: all equal (uniform branch)
        out[(size_t)row * NPOOL + t] = vmin;
        return;
    }

    // phase 1: histogram
    const float bscale = (float)NBIN / (vmax - vmin);
#pragma unroll
    for (int i = 0; i < 16; i++) {
        int bb = (int)((v[i] - vmin) * bscale);
        bb = bb > NBIN - 1 ? NBIN - 1 : (bb < 0 ? 0 : bb);
        atomicAdd(&pref[PADI(bb)], 1u);
    }
    __syncthreads();

    // exclusive prefix over 8192 counts: 32 bins/thread, two-pass reload
    {
        // pass A: per-thread total
        uint32_t s = 0;
#pragma unroll
        for (int j = 0; j < 32; j++) s += pref[PADI(t * 32 + j)];
        uint32_t tot = s;
        // warp inclusive scan of totals
#pragma unroll
        for (int o = 1; o < 32; o <<= 1) {
            uint32_t x = __shfl_up_sync(0xFFFFFFFFu, s, o);
            if ((t & 31) >= o) s += x;
        }
        if ((t & 31) == 31) wsum[t >> 5] = s;
        __syncthreads();
        uint32_t base = 0;
        for (int w = 0; w < (t >> 5); w++) base += wsum[w];
        uint32_t run = base + s - tot;               // exclusive start for my 32 bins
        __syncthreads();                             // all pass-A reads done
        // pass B: reload counts, write running exclusive prefix
#pragma unroll
        for (int j = 0; j < 32; j++) {
            uint32_t c = pref[PADI(t * 32 + j)];
            pref[PADI(t * 32 + j)] = run;
            run += c;
        }
        if (t == 0) pref[PADI(NBIN)] = M_;
    }
    __syncthreads();

    // rank -> bucket; capture base/n/la BEFORE scatter mutates pref
    const float step = 4094.0f / 255.0f;
    int q = (int)rintf(fmaf((float)t, step, 1.0f));
    if (q < 1) q = 1; if (q > M_ - 1) q = M_ - 1;
    const uint32_t a = (uint32_t)(M_ - 1 - q);
    int lo = 0, hi = NBIN - 1;
    while (lo < hi) {
        int mid = (lo + hi + 1) >> 1;
        if (pref[PADI(mid)] <= a) lo = mid; else hi = mid - 1;
    }
    const uint32_t mybase = pref[PADI(lo)];
    const uint32_t n  = pref[PADI(lo + 1)] - mybase;
    const uint32_t la = a - mybase;
    __syncthreads();                                 // searches done before scatter

    // phase 2: scatter raw values (bin recomputed, bit-identical formula)
#pragma unroll
    for (int i = 0; i < 16; i++) {
        int bb = (int)((v[i] - vmin) * bscale);
        bb = bb > NBIN - 1 ? NBIN - 1 : (bb < 0 ? 0 : bb);
        uint32_t pos = atomicAdd(&pref[PADI(bb)], 1u);
        cand[pos] = v[i];
    }
    __syncthreads();

    // exact la-th smallest among cand[mybase .. mybase+n)  (n ~ 4 now)
    float myval = cand[mybase];
    for (uint32_t i = 0; i < n; i++) {
        float ki = cand[mybase + i];
        uint32_t r = 0;
        for (uint32_t j = 0; j < n; j++) {
            float kj = cand[mybase + j];
            r += (kj < ki) || (kj == ki && j < i);
        }
        if (r == la) { myval = ki; break; }
    }
    out[(size_t)row * NPOOL + t] = myval;
}

// ---------------------------------------------------------------------------
// Launch
// ---------------------------------------------------------------------------
extern "C" void kernel_launch(void* const* d_in, const int* in_sizes, int n_in,
                              void* d_out, int out_size) {
    (void)in_sizes; (void)n_in; (void)out_size;
    const float* x = (const float*)d_in[0];
    float* out = (float*)d_out;

    convert_kernel<<<(BATCH * M_ * C_ / 2) / 256, 256>>>(x);

    dim3 ggrid(NTRI, 1, BATCH);
    gemm_mma_kernel<<<ggrid, 256>>>();

    cudaFuncSetAttribute(select_kernel, cudaFuncAttributeMaxDynamicSharedMemorySize, SEL_SMEM);
    select_kernel<<<BATCH * M_, 256, SEL_SMEM>>>(out);
}